// round 1
// baseline (speedup 1.0000x reference)
#include <cuda_runtime.h>
#include <math.h>

// Problem constants
constexpr int BATCH = 4;
constexpr int SEQ   = 2048;
constexpr int DIM   = 1024;
constexpr int NHEAD = 16;
constexpr int HDIM  = 64;            // DK
constexpr int NTOK  = BATCH * SEQ;   // 8192
constexpr int BHS   = BATCH * NHEAD; // 64

// Scratch (device globals: no allocation allowed in kernel_launch)
__device__ float g_q[BATCH * NHEAD * SEQ * HDIM]; // [b,h,s,dk]
__device__ float g_k[BATCH * NHEAD * SEQ * HDIM];
__device__ float g_v[BATCH * NHEAD * SEQ * HDIM];
__device__ float g_x[NTOK * DIM];                 // attn out, [b,s,h*dk]

// ---------------------------------------------------------------------------
// Tiled FP32 GEMM: C = A @ W^T, A [M=8192, K=1024] row-major, W [N,K] row-major
// BM=BN=64, BK=16, 256 threads, 4x4 per-thread tile.
// MODE 0: scatter output to [b,h,s,dk] layout (QKV). MODE 1: plain row-major.
// ---------------------------------------------------------------------------
constexpr int BM = 64, BN = 64, BK = 16;

template <int MODE>
__device__ __forceinline__ void gemm_body(const float* __restrict__ A,
                                          const float* __restrict__ W,
                                          float* __restrict__ C)
{
    __shared__ float As[BK][BM];
    __shared__ float Bs[BK][BN];

    const int tid = threadIdx.x;
    const int m0 = blockIdx.y * BM;
    const int n0 = blockIdx.x * BN;

    const int lr = tid >> 2;         // 0..63 (row within tile for loading)
    const int lc = (tid & 3) * 4;    // 0,4,8,12 (k-col group)
    const int tx = tid & 15;         // 0..15
    const int ty = tid >> 4;         // 0..15

    float acc[4][4] = {};

    for (int k0 = 0; k0 < DIM; k0 += BK) {
        float4 av = *(const float4*)(A + (size_t)(m0 + lr) * DIM + k0 + lc);
        float4 wv = *(const float4*)(W + (size_t)(n0 + lr) * DIM + k0 + lc);
        __syncthreads();  // previous compute done before overwriting smem
        As[lc + 0][lr] = av.x; As[lc + 1][lr] = av.y;
        As[lc + 2][lr] = av.z; As[lc + 3][lr] = av.w;
        Bs[lc + 0][lr] = wv.x; Bs[lc + 1][lr] = wv.y;
        Bs[lc + 2][lr] = wv.z; Bs[lc + 3][lr] = wv.w;
        __syncthreads();

        #pragma unroll
        for (int k = 0; k < BK; k++) {
            float4 a = *(const float4*)(&As[k][ty * 4]);
            float4 b = *(const float4*)(&Bs[k][tx * 4]);
            acc[0][0] = fmaf(a.x, b.x, acc[0][0]);
            acc[0][1] = fmaf(a.x, b.y, acc[0][1]);
            acc[0][2] = fmaf(a.x, b.z, acc[0][2]);
            acc[0][3] = fmaf(a.x, b.w, acc[0][3]);
            acc[1][0] = fmaf(a.y, b.x, acc[1][0]);
            acc[1][1] = fmaf(a.y, b.y, acc[1][1]);
            acc[1][2] = fmaf(a.y, b.z, acc[1][2]);
            acc[1][3] = fmaf(a.y, b.w, acc[1][3]);
            acc[2][0] = fmaf(a.z, b.x, acc[2][0]);
            acc[2][1] = fmaf(a.z, b.y, acc[2][1]);
            acc[2][2] = fmaf(a.z, b.z, acc[2][2]);
            acc[2][3] = fmaf(a.z, b.w, acc[2][3]);
            acc[3][0] = fmaf(a.w, b.x, acc[3][0]);
            acc[3][1] = fmaf(a.w, b.y, acc[3][1]);
            acc[3][2] = fmaf(a.w, b.z, acc[3][2]);
            acc[3][3] = fmaf(a.w, b.w, acc[3][3]);
        }
    }

    #pragma unroll
    for (int i = 0; i < 4; i++) {
        const int m = m0 + ty * 4 + i;
        const int n = n0 + tx * 4;
        float4 r = make_float4(acc[i][0], acc[i][1], acc[i][2], acc[i][3]);
        if (MODE == 0) {
            // token m -> (b, s); out-col n -> (h, dk). write [b,h,s,dk]
            const int b = m >> 11, s = m & (SEQ - 1);
            const int h = n >> 6, dk = n & (HDIM - 1);
            float* p = C + ((size_t)(b * NHEAD + h) * SEQ + s) * HDIM + dk;
            *(float4*)p = r;
        } else {
            *(float4*)(C + (size_t)m * DIM + n) = r;
        }
    }
}

__global__ void __launch_bounds__(256)
gemm_qkv(const float* __restrict__ Aq, const float* __restrict__ Ak,
         const float* __restrict__ Av, const float* __restrict__ Wq,
         const float* __restrict__ Wk, const float* __restrict__ Wv)
{
    const int sel = blockIdx.z;
    const float* A = (sel == 0) ? Aq : (sel == 1) ? Ak : Av;
    const float* W = (sel == 0) ? Wq : (sel == 1) ? Wk : Wv;
    float* C = (sel == 0) ? g_q : (sel == 1) ? g_k : g_v;
    gemm_body<0>(A, W, C);
}

__global__ void __launch_bounds__(256)
gemm_out(const float* __restrict__ Wo, float* __restrict__ C)
{
    gemm_body<1>(g_x, Wo, C);
}

// ---------------------------------------------------------------------------
// RoPE (interleaved, rotate_half on (d/2,2) pairs, freqs repeated pairwise)
// Applied in-place to g_q and g_k (blockIdx.y selects). One thread = one pair.
// ---------------------------------------------------------------------------
__global__ void __launch_bounds__(256)
rope_kernel()
{
    float* X = blockIdx.y ? g_k : g_q;
    const size_t idx = (size_t)blockIdx.x * blockDim.x + threadIdx.x;
    const int j = (int)(idx & 31);           // pair index 0..31
    const size_t row = idx >> 5;             // (b*H+h)*S + s
    const int s = (int)(row & (SEQ - 1));

    // inv_freq = 1 / 10000^(2j/64), match reference fp32 path
    const float e = (float)(2 * j) * (1.0f / 64.0f);
    const float inv_freq = 1.0f / powf(10000.0f, e);
    const float ang = (float)s * inv_freq;
    float sn, cs;
    sincosf(ang, &sn, &cs);

    float2 x = *(float2*)(X + row * HDIM + 2 * j);
    float2 y;
    y.x = x.x * cs - x.y * sn;
    y.y = x.y * cs + x.x * sn;
    *(float2*)(X + row * HDIM + 2 * j) = y;
}

// ---------------------------------------------------------------------------
// Flash attention (fp32): 1 thread = 1 query row, K/V tiles (64 keys) in SMEM.
// Online softmax, rescale only when the running max changes.
// Writes attention output to g_x in [b, s, h*dk] layout for the O projection.
// ---------------------------------------------------------------------------
constexpr int KT = 64;  // keys per smem tile

__global__ void __launch_bounds__(128)
attn_kernel(const int* __restrict__ mask)
{
    __shared__ float Ks[KT * HDIM];
    __shared__ float Vs[KT * HDIM];
    __shared__ float Mk[KT];   // 1.0f if masked (mask==0), else 0.0f

    const int bh = blockIdx.y;                          // 0..63
    const int b = bh >> 4;
    const int h = bh & (NHEAD - 1);
    const int qrow = blockIdx.x * 128 + threadIdx.x;    // 0..2047

    const float* qptr = g_q + ((size_t)bh * SEQ + qrow) * HDIM;
    const float* kbase = g_k + (size_t)bh * SEQ * HDIM;
    const float* vbase = g_v + (size_t)bh * SEQ * HDIM;

    float q[HDIM];
    #pragma unroll
    for (int d = 0; d < HDIM; d += 4) {
        float4 t = *(const float4*)(qptr + d);
        q[d] = t.x; q[d + 1] = t.y; q[d + 2] = t.z; q[d + 3] = t.w;
    }

    float acc[HDIM];
    #pragma unroll
    for (int d = 0; d < HDIM; d++) acc[d] = 0.0f;
    float m = -INFINITY;
    float l = 0.0f;

    for (int kt = 0; kt < SEQ; kt += KT) {
        __syncthreads();
        const float4* ksrc = (const float4*)(kbase + (size_t)kt * HDIM);
        const float4* vsrc = (const float4*)(vbase + (size_t)kt * HDIM);
        #pragma unroll
        for (int i = threadIdx.x; i < KT * HDIM / 4; i += 128) {
            ((float4*)Ks)[i] = ksrc[i];
            ((float4*)Vs)[i] = vsrc[i];
        }
        if (threadIdx.x < KT)
            Mk[threadIdx.x] = (mask[b * SEQ + kt + threadIdx.x] == 0) ? 1.0f : 0.0f;
        __syncthreads();

        for (int j = 0; j < KT; j++) {
            const float* kr = Ks + j * HDIM;
            float s0 = 0.f, s1 = 0.f, s2 = 0.f, s3 = 0.f;
            #pragma unroll
            for (int d = 0; d < HDIM; d += 4) {
                float4 kv = *(const float4*)(kr + d);
                s0 = fmaf(q[d],     kv.x, s0);
                s1 = fmaf(q[d + 1], kv.y, s1);
                s2 = fmaf(q[d + 2], kv.z, s2);
                s3 = fmaf(q[d + 3], kv.w, s3);
            }
            float s = ((s0 + s1) + (s2 + s3)) * 0.125f;   // 1/sqrt(64)
            if (Mk[j] != 0.0f) s = -10000.0f;

            const float mnew = fmaxf(m, s);
            if (mnew > m) {
                const float corr = __expf(m - mnew);      // exp(-inf)=0 on first hit
                l *= corr;
                #pragma unroll
                for (int d = 0; d < HDIM; d++) acc[d] *= corr;
                m = mnew;
            }
            const float p = __expf(s - m);
            l += p;

            const float* vr = Vs + j * HDIM;
            #pragma unroll
            for (int d = 0; d < HDIM; d += 4) {
                float4 vv = *(const float4*)(vr + d);
                acc[d]     = fmaf(p, vv.x, acc[d]);
                acc[d + 1] = fmaf(p, vv.y, acc[d + 1]);
                acc[d + 2] = fmaf(p, vv.z, acc[d + 2]);
                acc[d + 3] = fmaf(p, vv.w, acc[d + 3]);
            }
        }
    }

    const float inv = 1.0f / l;
    float* op = g_x + ((size_t)(b * SEQ + qrow)) * DIM + h * HDIM;
    #pragma unroll
    for (int d = 0; d < HDIM; d += 4) {
        float4 t = make_float4(acc[d] * inv, acc[d + 1] * inv,
                               acc[d + 2] * inv, acc[d + 3] * inv);
        *(float4*)(op + d) = t;
    }
}

// ---------------------------------------------------------------------------
// Launch
// ---------------------------------------------------------------------------
extern "C" void kernel_launch(void* const* d_in, const int* in_sizes, int n_in,
                              void* d_out, int out_size)
{
    const float* q    = (const float*)d_in[0];
    const float* k    = (const float*)d_in[1];
    const float* v    = (const float*)d_in[2];
    const int*   mask = (const int*)  d_in[3];
    const float* w_q  = (const float*)d_in[4];
    const float* w_k  = (const float*)d_in[5];
    const float* w_v  = (const float*)d_in[6];
    const float* w_o  = (const float*)d_in[7];
    float* out = (float*)d_out;

    // 1) Q/K/V projections (writes [b,h,s,dk] scratch)
    dim3 g1(DIM / BN, NTOK / BM, 3);
    gemm_qkv<<<g1, 256>>>(q, k, v, w_q, w_k, w_v);

    // 2) RoPE on Q and K in-place
    // pairs per tensor = BHS*SEQ*32 = 4,194,304 -> 16384 blocks of 256
    dim3 g2((BHS * SEQ * 32) / 256, 2);
    rope_kernel<<<g2, 256>>>();

    // 3) Attention (reads g_q/g_k/g_v, writes g_x in [b,s,h*dk])
    dim3 g3(SEQ / 128, BHS);
    attn_kernel<<<g3, 128>>>(mask);

    // 4) Output projection
    dim3 g4(DIM / BN, NTOK / BM);
    gemm_out<<<g4, 256>>>(w_o, out);
}

// round 3
// speedup vs baseline: 1.4211x; 1.4211x over previous
#include <cuda_runtime.h>
#include <cuda_bf16.h>
#include <math.h>
#include <stdint.h>

// Problem constants
constexpr int BATCH = 4;
constexpr int SEQ   = 2048;
constexpr int DIM   = 1024;
constexpr int NHEAD = 16;
constexpr int HDIM  = 64;            // DK
constexpr int NTOK  = BATCH * SEQ;   // 8192
constexpr int BHS   = BATCH * NHEAD; // 64

// Scratch (device globals: no allocation allowed in kernel_launch)
__device__ float g_q[BATCH * NHEAD * SEQ * HDIM]; // [b,h,s,dk]
__device__ float g_k[BATCH * NHEAD * SEQ * HDIM];
__device__ float g_v[BATCH * NHEAD * SEQ * HDIM];
__device__ float g_x[NTOK * DIM];                 // attn out, [b,s,h*dk]

// ===========================================================================
// mma.sync bf16 split-3 GEMM: C = A @ W^T
// A [8192,1024] row-major, W [1024,1024] row-major ([out,in] -> B col-major)
// fp32 precision via a = ah + al (bf16): D += Ah*Bh + Ah*Bl + Al*Bh
// CTA tile 128x128, 8 warps (2M x 4N), warp tile 64x32, K staged 32 wide.
// ===========================================================================
constexpr int TKS = 32;                 // K per smem stage
constexpr int NST = DIM / TKS;          // 32 stages
constexpr int PITCH = 40;               // bf16 elems per smem row (32 + 8 pad)

__device__ __forceinline__ uint32_t smem_u32(const void* p) {
    uint32_t a;
    asm("{ .reg .u64 t; cvta.to.shared.u64 t, %1; cvt.u32.u64 %0, t; }"
        : "=r"(a) : "l"(p));
    return a;
}

__device__ __forceinline__ void ldm_x4(uint32_t* r, uint32_t addr) {
    asm volatile("ldmatrix.sync.aligned.m8n8.x4.shared.b16 {%0,%1,%2,%3}, [%4];"
        : "=r"(r[0]), "=r"(r[1]), "=r"(r[2]), "=r"(r[3]) : "r"(addr));
}

__device__ __forceinline__ void ldm_x2(uint32_t* r, uint32_t addr) {
    asm volatile("ldmatrix.sync.aligned.m8n8.x2.shared.b16 {%0,%1}, [%2];"
        : "=r"(r[0]), "=r"(r[1]) : "r"(addr));
}

__device__ __forceinline__ void mma16816(float* c, const uint32_t* a, const uint32_t* b) {
    asm volatile(
        "mma.sync.aligned.m16n8k16.row.col.f32.bf16.bf16.f32 "
        "{%0,%1,%2,%3}, {%4,%5,%6,%7}, {%8,%9}, {%0,%1,%2,%3};"
        : "+f"(c[0]), "+f"(c[1]), "+f"(c[2]), "+f"(c[3])
        : "r"(a[0]), "r"(a[1]), "r"(a[2]), "r"(a[3]), "r"(b[0]), "r"(b[1]));
}

// float4 -> 2x (bf16x2 hi) + 2x (bf16x2 lo)
__device__ __forceinline__ void cvt_hl(float4 v, uint2& hi, uint2& lo) {
    __nv_bfloat162 h0 = __floats2bfloat162_rn(v.x, v.y);
    __nv_bfloat162 h1 = __floats2bfloat162_rn(v.z, v.w);
    float2 f0 = __bfloat1622float2(h0);
    float2 f1 = __bfloat1622float2(h1);
    __nv_bfloat162 l0 = __floats2bfloat162_rn(v.x - f0.x, v.y - f0.y);
    __nv_bfloat162 l1 = __floats2bfloat162_rn(v.z - f1.x, v.w - f1.y);
    hi.x = *(uint32_t*)&h0; hi.y = *(uint32_t*)&h1;
    lo.x = *(uint32_t*)&l0; lo.y = *(uint32_t*)&l1;
}

// MODE 0: scatter C to [b,h,s,dk] (QKV).  MODE 1: row-major (O proj).
template <int MODE>
__device__ __forceinline__ void gemm_mma_body(const float* __restrict__ A,
                                              const float* __restrict__ W,
                                              float* __restrict__ C)
{
    __shared__ __align__(16) __nv_bfloat16 sAh[128 * PITCH];
    __shared__ __align__(16) __nv_bfloat16 sAl[128 * PITCH];
    __shared__ __align__(16) __nv_bfloat16 sBh[128 * PITCH];
    __shared__ __align__(16) __nv_bfloat16 sBl[128 * PITCH];

    const int tid  = threadIdx.x;
    const int wid  = tid >> 5;
    const int lane = tid & 31;
    const int wm   = wid & 1;        // warp M index (0..1), 64 rows each
    const int wn   = wid >> 1;       // warp N index (0..3), 32 cols each
    const int m0   = blockIdx.y * 128;
    const int n0   = blockIdx.x * 128;

    // global load mapping: thread -> row tid>>1, col half (tid&1)*16 (fp32)
    const int lrow = tid >> 1;
    const int lcol = (tid & 1) * 16;
    const float4* arow = (const float4*)(A + (size_t)(m0 + lrow) * DIM + lcol);
    const float4* brow = (const float4*)(W + (size_t)(n0 + lrow) * DIM + lcol);
    // smem store base offsets (bf16 elems)
    const int soff = lrow * PITCH + lcol;

    // ldmatrix fragment addresses (bytes)
    const uint32_t aAh = smem_u32(sAh), aAl = smem_u32(sAl);
    const uint32_t aBh = smem_u32(sBh), aBl = smem_u32(sBl);
    const int a_r = wm * 64 + (lane & 15);           // + mi*16
    const int a_c = (lane >> 4) * 8;                 // + ks*16
    const int b_r = wn * 32 + (lane & 7);            // + ni*8
    const int b_c = ((lane >> 3) & 1) * 8;           // + ks*16

    float acc[4][4][4];
    #pragma unroll
    for (int i = 0; i < 4; i++)
        #pragma unroll
        for (int j = 0; j < 4; j++)
            #pragma unroll
            for (int q = 0; q < 4; q++) acc[i][j][q] = 0.0f;

    float4 ra[4], rb[4];
    // prologue: load + store stage 0
    #pragma unroll
    for (int i = 0; i < 4; i++) {
        ra[i] = arow[i + 0];
        rb[i] = brow[i + 0];
    }
    #pragma unroll
    for (int i = 0; i < 4; i++) {
        uint2 hi, lo;
        cvt_hl(ra[i], hi, lo);
        *(uint2*)(sAh + soff + i * 4) = hi;
        *(uint2*)(sAl + soff + i * 4) = lo;
        cvt_hl(rb[i], hi, lo);
        *(uint2*)(sBh + soff + i * 4) = hi;
        *(uint2*)(sBl + soff + i * 4) = lo;
    }
    __syncthreads();

    for (int s = 0; s < NST; s++) {
        // prefetch next stage into registers
        if (s + 1 < NST) {
            const int koff = ((s + 1) * TKS) >> 2;   // in float4 units
            #pragma unroll
            for (int i = 0; i < 4; i++) {
                ra[i] = arow[koff + i];
                rb[i] = brow[koff + i];
            }
        }

        // compute stage s: 2 k16 steps
        #pragma unroll
        for (int ks = 0; ks < 2; ks++) {
            uint32_t Ah[4][4], Al[4][4], Bh[4][2], Bl[4][2];
            const int ac = ks * 16 + a_c;
            const int bc = ks * 16 + b_c;
            #pragma unroll
            for (int mi = 0; mi < 4; mi++) {
                const uint32_t off = ((a_r + mi * 16) * PITCH + ac) * 2;
                ldm_x4(Ah[mi], aAh + off);
                ldm_x4(Al[mi], aAl + off);
            }
            #pragma unroll
            for (int ni = 0; ni < 4; ni++) {
                const uint32_t off = ((b_r + ni * 8) * PITCH + bc) * 2;
                ldm_x2(Bh[ni], aBh + off);
                ldm_x2(Bl[ni], aBl + off);
            }
            #pragma unroll
            for (int mi = 0; mi < 4; mi++)
                #pragma unroll
                for (int ni = 0; ni < 4; ni++) {
                    mma16816(acc[mi][ni], Ah[mi], Bh[ni]);
                    mma16816(acc[mi][ni], Ah[mi], Bl[ni]);
                    mma16816(acc[mi][ni], Al[mi], Bh[ni]);
                }
        }
        __syncthreads();

        if (s + 1 < NST) {
            #pragma unroll
            for (int i = 0; i < 4; i++) {
                uint2 hi, lo;
                cvt_hl(ra[i], hi, lo);
                *(uint2*)(sAh + soff + i * 4) = hi;
                *(uint2*)(sAl + soff + i * 4) = lo;
                cvt_hl(rb[i], hi, lo);
                *(uint2*)(sBh + soff + i * 4) = hi;
                *(uint2*)(sBl + soff + i * 4) = lo;
            }
            __syncthreads();
        }
    }

    // epilogue: c0,c1 -> (r, c), c2,c3 -> (r+8, c); c even pair
    const int er = m0 + wm * 64 + (lane >> 2);
    const int ec = n0 + wn * 32 + (lane & 3) * 2;
    #pragma unroll
    for (int mi = 0; mi < 4; mi++) {
        #pragma unroll
        for (int ni = 0; ni < 4; ni++) {
            const int col = ec + ni * 8;
            #pragma unroll
            for (int half = 0; half < 2; half++) {
                const int row = er + mi * 16 + half * 8;
                float2 v = make_float2(acc[mi][ni][half * 2],
                                       acc[mi][ni][half * 2 + 1]);
                if (MODE == 0) {
                    const int b = row >> 11, sq = row & (SEQ - 1);
                    const int h = col >> 6, dk = col & (HDIM - 1);
                    *(float2*)(C + ((size_t)(b * NHEAD + h) * SEQ + sq) * HDIM + dk) = v;
                } else {
                    *(float2*)(C + (size_t)row * DIM + col) = v;
                }
            }
        }
    }
}

__global__ void __launch_bounds__(256, 1)
gemm_qkv_tc(const float* __restrict__ Aq, const float* __restrict__ Ak,
            const float* __restrict__ Av, const float* __restrict__ Wq,
            const float* __restrict__ Wk, const float* __restrict__ Wv)
{
    const int sel = blockIdx.z;
    const float* A = (sel == 0) ? Aq : (sel == 1) ? Ak : Av;
    const float* W = (sel == 0) ? Wq : (sel == 1) ? Wk : Wv;
    float* C = (sel == 0) ? g_q : (sel == 1) ? g_k : g_v;
    gemm_mma_body<0>(A, W, C);
}

__global__ void __launch_bounds__(256, 1)
gemm_out_tc(const float* __restrict__ Wo, float* __restrict__ C)
{
    gemm_mma_body<1>(g_x, Wo, C);
}

// ---------------------------------------------------------------------------
// RoPE (interleaved pairs), in-place on g_q / g_k
// ---------------------------------------------------------------------------
__global__ void __launch_bounds__(256)
rope_kernel()
{
    float* X = blockIdx.y ? g_k : g_q;
    const size_t idx = (size_t)blockIdx.x * blockDim.x + threadIdx.x;
    const int j = (int)(idx & 31);
    const size_t row = idx >> 5;
    const int s = (int)(row & (SEQ - 1));

    const float e = (float)(2 * j) * (1.0f / 64.0f);
    const float inv_freq = 1.0f / powf(10000.0f, e);
    const float ang = (float)s * inv_freq;
    float sn, cs;
    sincosf(ang, &sn, &cs);

    float2 x = *(float2*)(X + row * HDIM + 2 * j);
    float2 y;
    y.x = x.x * cs - x.y * sn;
    y.y = x.y * cs + x.x * sn;
    *(float2*)(X + row * HDIM + 2 * j) = y;
}

// ---------------------------------------------------------------------------
// Flash attention (fp32), 1 thread = 1 query row, K/V tiles in SMEM
// ---------------------------------------------------------------------------
constexpr int KT = 64;

__global__ void __launch_bounds__(128)
attn_kernel(const int* __restrict__ mask)
{
    __shared__ float Ks[KT * HDIM];
    __shared__ float Vs[KT * HDIM];
    __shared__ float Mk[KT];

    const int bh = blockIdx.y;
    const int b = bh >> 4;
    const int h = bh & (NHEAD - 1);
    const int qrow = blockIdx.x * 128 + threadIdx.x;

    const float* qptr = g_q + ((size_t)bh * SEQ + qrow) * HDIM;
    const float* kbase = g_k + (size_t)bh * SEQ * HDIM;
    const float* vbase = g_v + (size_t)bh * SEQ * HDIM;

    float q[HDIM];
    #pragma unroll
    for (int d = 0; d < HDIM; d += 4) {
        float4 t = *(const float4*)(qptr + d);
        q[d] = t.x; q[d + 1] = t.y; q[d + 2] = t.z; q[d + 3] = t.w;
    }

    float acc[HDIM];
    #pragma unroll
    for (int d = 0; d < HDIM; d++) acc[d] = 0.0f;
    float m = -INFINITY;
    float l = 0.0f;

    for (int kt = 0; kt < SEQ; kt += KT) {
        __syncthreads();
        const float4* ksrc = (const float4*)(kbase + (size_t)kt * HDIM);
        const float4* vsrc = (const float4*)(vbase + (size_t)kt * HDIM);
        #pragma unroll
        for (int i = threadIdx.x; i < KT * HDIM / 4; i += 128) {
            ((float4*)Ks)[i] = ksrc[i];
            ((float4*)Vs)[i] = vsrc[i];
        }
        if (threadIdx.x < KT)
            Mk[threadIdx.x] = (mask[b * SEQ + kt + threadIdx.x] == 0) ? 1.0f : 0.0f;
        __syncthreads();

        for (int j = 0; j < KT; j++) {
            const float* kr = Ks + j * HDIM;
            float s0 = 0.f, s1 = 0.f, s2 = 0.f, s3 = 0.f;
            #pragma unroll
            for (int d = 0; d < HDIM; d += 4) {
                float4 kv = *(const float4*)(kr + d);
                s0 = fmaf(q[d],     kv.x, s0);
                s1 = fmaf(q[d + 1], kv.y, s1);
                s2 = fmaf(q[d + 2], kv.z, s2);
                s3 = fmaf(q[d + 3], kv.w, s3);
            }
            float s = ((s0 + s1) + (s2 + s3)) * 0.125f;
            if (Mk[j] != 0.0f) s = -10000.0f;

            const float mnew = fmaxf(m, s);
            if (mnew > m) {
                const float corr = __expf(m - mnew);
                l *= corr;
                #pragma unroll
                for (int d = 0; d < HDIM; d++) acc[d] *= corr;
                m = mnew;
            }
            const float p = __expf(s - m);
            l += p;

            const float* vr = Vs + j * HDIM;
            #pragma unroll
            for (int d = 0; d < HDIM; d += 4) {
                float4 vv = *(const float4*)(vr + d);
                acc[d]     = fmaf(p, vv.x, acc[d]);
                acc[d + 1] = fmaf(p, vv.y, acc[d + 1]);
                acc[d + 2] = fmaf(p, vv.z, acc[d + 2]);
                acc[d + 3] = fmaf(p, vv.w, acc[d + 3]);
            }
        }
    }

    const float inv = 1.0f / l;
    float* op = g_x + ((size_t)(b * SEQ + qrow)) * DIM + h * HDIM;
    #pragma unroll
    for (int d = 0; d < HDIM; d += 4) {
        float4 t = make_float4(acc[d] * inv, acc[d + 1] * inv,
                               acc[d + 2] * inv, acc[d + 3] * inv);
        *(float4*)(op + d) = t;
    }
}

// ---------------------------------------------------------------------------
// Launch
// ---------------------------------------------------------------------------
extern "C" void kernel_launch(void* const* d_in, const int* in_sizes, int n_in,
                              void* d_out, int out_size)
{
    const float* q    = (const float*)d_in[0];
    const float* k    = (const float*)d_in[1];
    const float* v    = (const float*)d_in[2];
    const int*   mask = (const int*)  d_in[3];
    const float* w_q  = (const float*)d_in[4];
    const float* w_k  = (const float*)d_in[5];
    const float* w_v  = (const float*)d_in[6];
    const float* w_o  = (const float*)d_in[7];
    float* out = (float*)d_out;

    // 1) Q/K/V projections on tensor cores (writes [b,h,s,dk] scratch)
    dim3 g1(DIM / 128, NTOK / 128, 3);
    gemm_qkv_tc<<<g1, 256>>>(q, k, v, w_q, w_k, w_v);

    // 2) RoPE on Q and K in-place
    dim3 g2((BHS * SEQ * 32) / 256, 2);
    rope_kernel<<<g2, 256>>>();

    // 3) Attention
    dim3 g3(SEQ / 128, BHS);
    attn_kernel<<<g3, 128>>>(mask);

    // 4) Output projection on tensor cores
    dim3 g4(DIM / 128, NTOK / 128);
    gemm_out_tc<<<g4, 256>>>(w_o, out);
}

// round 4
// speedup vs baseline: 3.0573x; 2.1513x over previous
#include <cuda_runtime.h>
#include <cuda_bf16.h>
#include <math.h>
#include <stdint.h>

// Problem constants
constexpr int BATCH = 4;
constexpr int SEQ   = 2048;
constexpr int DIM   = 1024;
constexpr int NHEAD = 16;
constexpr int HDIM  = 64;            // DK
constexpr int NTOK  = BATCH * SEQ;   // 8192
constexpr int BHS   = BATCH * NHEAD; // 64

// Scratch (device globals: no allocation allowed in kernel_launch)
__device__ float g_q[BATCH * NHEAD * SEQ * HDIM]; // [b,h,s,dk]
__device__ float g_k[BATCH * NHEAD * SEQ * HDIM];
__device__ float g_v[BATCH * NHEAD * SEQ * HDIM];
__device__ float g_x[NTOK * DIM];                 // attn out, [b,s,h*dk]

// ===========================================================================
// Common helpers
// ===========================================================================
__device__ __forceinline__ uint32_t smem_u32(const void* p) {
    uint32_t a;
    asm("{ .reg .u64 t; cvta.to.shared.u64 t, %1; cvt.u32.u64 %0, t; }"
        : "=r"(a) : "l"(p));
    return a;
}

__device__ __forceinline__ void ldm_x4(uint32_t* r, uint32_t addr) {
    asm volatile("ldmatrix.sync.aligned.m8n8.x4.shared.b16 {%0,%1,%2,%3}, [%4];"
        : "=r"(r[0]), "=r"(r[1]), "=r"(r[2]), "=r"(r[3]) : "r"(addr));
}

__device__ __forceinline__ void ldm_x4_t(uint32_t* r, uint32_t addr) {
    asm volatile("ldmatrix.sync.aligned.m8n8.x4.trans.shared.b16 {%0,%1,%2,%3}, [%4];"
        : "=r"(r[0]), "=r"(r[1]), "=r"(r[2]), "=r"(r[3]) : "r"(addr));
}

__device__ __forceinline__ void ldm_x2(uint32_t* r, uint32_t addr) {
    asm volatile("ldmatrix.sync.aligned.m8n8.x2.shared.b16 {%0,%1}, [%2];"
        : "=r"(r[0]), "=r"(r[1]) : "r"(addr));
}

__device__ __forceinline__ void mma16816(float* c, const uint32_t* a, const uint32_t* b) {
    asm volatile(
        "mma.sync.aligned.m16n8k16.row.col.f32.bf16.bf16.f32 "
        "{%0,%1,%2,%3}, {%4,%5,%6,%7}, {%8,%9}, {%0,%1,%2,%3};"
        : "+f"(c[0]), "+f"(c[1]), "+f"(c[2]), "+f"(c[3])
        : "r"(a[0]), "r"(a[1]), "r"(a[2]), "r"(a[3]), "r"(b[0]), "r"(b[1]));
}

// float4 -> 2x (bf16x2 hi) + 2x (bf16x2 lo)
__device__ __forceinline__ void cvt_hl(float4 v, uint2& hi, uint2& lo) {
    __nv_bfloat162 h0 = __floats2bfloat162_rn(v.x, v.y);
    __nv_bfloat162 h1 = __floats2bfloat162_rn(v.z, v.w);
    float2 f0 = __bfloat1622float2(h0);
    float2 f1 = __bfloat1622float2(h1);
    __nv_bfloat162 l0 = __floats2bfloat162_rn(v.x - f0.x, v.y - f0.y);
    __nv_bfloat162 l1 = __floats2bfloat162_rn(v.z - f1.x, v.w - f1.y);
    hi.x = *(uint32_t*)&h0; hi.y = *(uint32_t*)&h1;
    lo.x = *(uint32_t*)&l0; lo.y = *(uint32_t*)&l1;
}

// two floats -> bf16x2 hi + bf16x2 lo (residual)
__device__ __forceinline__ void pack_hl(float a, float b, uint32_t& hi, uint32_t& lo) {
    __nv_bfloat162 h = __floats2bfloat162_rn(a, b);
    float2 hf = __bfloat1622float2(h);
    __nv_bfloat162 l = __floats2bfloat162_rn(a - hf.x, b - hf.y);
    hi = *(uint32_t*)&h;
    lo = *(uint32_t*)&l;
}

// FFMA-only exp2 (no MUFU): degree-5 poly + exponent injection. y<=0 assumed.
__device__ __forceinline__ float exp2fast(float y) {
    y = fmaxf(y, -80.0f);
    float t = y + 12582912.0f;          // round-to-nearest integer (2^23*1.5)
    float n = t - 12582912.0f;
    float f = y - n;                    // [-0.5, 0.5]
    float p = 0.0013333558f;
    p = fmaf(p, f, 0.0096181291f);
    p = fmaf(p, f, 0.0555041087f);
    p = fmaf(p, f, 0.2402265069f);
    p = fmaf(p, f, 0.6931471806f);
    p = fmaf(p, f, 1.0f);
    return __int_as_float(__float_as_int(p) + (__float_as_int(t) << 23));
}

// ===========================================================================
// mma.sync bf16 split-3 GEMM: C = A @ W^T  (unchanged from R3, passing)
// ===========================================================================
constexpr int TKS = 32;
constexpr int NST = DIM / TKS;
constexpr int PITCH = 40;

template <int MODE>
__device__ __forceinline__ void gemm_mma_body(const float* __restrict__ A,
                                              const float* __restrict__ W,
                                              float* __restrict__ C)
{
    __shared__ __align__(16) __nv_bfloat16 sAh[128 * PITCH];
    __shared__ __align__(16) __nv_bfloat16 sAl[128 * PITCH];
    __shared__ __align__(16) __nv_bfloat16 sBh[128 * PITCH];
    __shared__ __align__(16) __nv_bfloat16 sBl[128 * PITCH];

    const int tid  = threadIdx.x;
    const int wid  = tid >> 5;
    const int lane = tid & 31;
    const int wm   = wid & 1;
    const int wn   = wid >> 1;
    const int m0   = blockIdx.y * 128;
    const int n0   = blockIdx.x * 128;

    const int lrow = tid >> 1;
    const int lcol = (tid & 1) * 16;
    const float4* arow = (const float4*)(A + (size_t)(m0 + lrow) * DIM + lcol);
    const float4* brow = (const float4*)(W + (size_t)(n0 + lrow) * DIM + lcol);
    const int soff = lrow * PITCH + lcol;

    const uint32_t aAh = smem_u32(sAh), aAl = smem_u32(sAl);
    const uint32_t aBh = smem_u32(sBh), aBl = smem_u32(sBl);
    const int a_r = wm * 64 + (lane & 15);
    const int a_c = (lane >> 4) * 8;
    const int b_r = wn * 32 + (lane & 7);
    const int b_c = ((lane >> 3) & 1) * 8;

    float acc[4][4][4];
    #pragma unroll
    for (int i = 0; i < 4; i++)
        #pragma unroll
        for (int j = 0; j < 4; j++)
            #pragma unroll
            for (int q = 0; q < 4; q++) acc[i][j][q] = 0.0f;

    float4 ra[4], rb[4];
    #pragma unroll
    for (int i = 0; i < 4; i++) { ra[i] = arow[i]; rb[i] = brow[i]; }
    #pragma unroll
    for (int i = 0; i < 4; i++) {
        uint2 hi, lo;
        cvt_hl(ra[i], hi, lo);
        *(uint2*)(sAh + soff + i * 4) = hi;
        *(uint2*)(sAl + soff + i * 4) = lo;
        cvt_hl(rb[i], hi, lo);
        *(uint2*)(sBh + soff + i * 4) = hi;
        *(uint2*)(sBl + soff + i * 4) = lo;
    }
    __syncthreads();

    for (int s = 0; s < NST; s++) {
        if (s + 1 < NST) {
            const int koff = ((s + 1) * TKS) >> 2;
            #pragma unroll
            for (int i = 0; i < 4; i++) { ra[i] = arow[koff + i]; rb[i] = brow[koff + i]; }
        }
        #pragma unroll
        for (int ks = 0; ks < 2; ks++) {
            uint32_t Ah[4][4], Al[4][4], Bh[4][2], Bl[4][2];
            const int ac = ks * 16 + a_c;
            const int bc = ks * 16 + b_c;
            #pragma unroll
            for (int mi = 0; mi < 4; mi++) {
                const uint32_t off = ((a_r + mi * 16) * PITCH + ac) * 2;
                ldm_x4(Ah[mi], aAh + off);
                ldm_x4(Al[mi], aAl + off);
            }
            #pragma unroll
            for (int ni = 0; ni < 4; ni++) {
                const uint32_t off = ((b_r + ni * 8) * PITCH + bc) * 2;
                ldm_x2(Bh[ni], aBh + off);
                ldm_x2(Bl[ni], aBl + off);
            }
            #pragma unroll
            for (int mi = 0; mi < 4; mi++)
                #pragma unroll
                for (int ni = 0; ni < 4; ni++) {
                    mma16816(acc[mi][ni], Ah[mi], Bh[ni]);
                    mma16816(acc[mi][ni], Ah[mi], Bl[ni]);
                    mma16816(acc[mi][ni], Al[mi], Bh[ni]);
                }
        }
        __syncthreads();
        if (s + 1 < NST) {
            #pragma unroll
            for (int i = 0; i < 4; i++) {
                uint2 hi, lo;
                cvt_hl(ra[i], hi, lo);
                *(uint2*)(sAh + soff + i * 4) = hi;
                *(uint2*)(sAl + soff + i * 4) = lo;
                cvt_hl(rb[i], hi, lo);
                *(uint2*)(sBh + soff + i * 4) = hi;
                *(uint2*)(sBl + soff + i * 4) = lo;
            }
            __syncthreads();
        }
    }

    const int er = m0 + wm * 64 + (lane >> 2);
    const int ec = n0 + wn * 32 + (lane & 3) * 2;
    #pragma unroll
    for (int mi = 0; mi < 4; mi++) {
        #pragma unroll
        for (int ni = 0; ni < 4; ni++) {
            const int col = ec + ni * 8;
            #pragma unroll
            for (int half = 0; half < 2; half++) {
                const int row = er + mi * 16 + half * 8;
                float2 v = make_float2(acc[mi][ni][half * 2],
                                       acc[mi][ni][half * 2 + 1]);
                if (MODE == 0) {
                    const int b = row >> 11, sq = row & (SEQ - 1);
                    const int h = col >> 6, dk = col & (HDIM - 1);
                    *(float2*)(C + ((size_t)(b * NHEAD + h) * SEQ + sq) * HDIM + dk) = v;
                } else {
                    *(float2*)(C + (size_t)row * DIM + col) = v;
                }
            }
        }
    }
}

__global__ void __launch_bounds__(256, 1)
gemm_qkv_tc(const float* __restrict__ Aq, const float* __restrict__ Ak,
            const float* __restrict__ Av, const float* __restrict__ Wq,
            const float* __restrict__ Wk, const float* __restrict__ Wv)
{
    const int sel = blockIdx.z;
    const float* A = (sel == 0) ? Aq : (sel == 1) ? Ak : Av;
    const float* W = (sel == 0) ? Wq : (sel == 1) ? Wk : Wv;
    float* C = (sel == 0) ? g_q : (sel == 1) ? g_k : g_v;
    gemm_mma_body<0>(A, W, C);
}

__global__ void __launch_bounds__(256, 1)
gemm_out_tc(const float* __restrict__ Wo, float* __restrict__ C)
{
    gemm_mma_body<1>(g_x, Wo, C);
}

// ---------------------------------------------------------------------------
// RoPE (interleaved pairs), in-place on g_q / g_k
// ---------------------------------------------------------------------------
__global__ void __launch_bounds__(256)
rope_kernel()
{
    float* X = blockIdx.y ? g_k : g_q;
    const size_t idx = (size_t)blockIdx.x * blockDim.x + threadIdx.x;
    const int j = (int)(idx & 31);
    const size_t row = idx >> 5;
    const int s = (int)(row & (SEQ - 1));

    const float e = (float)(2 * j) * (1.0f / 64.0f);
    const float inv_freq = 1.0f / powf(10000.0f, e);
    const float ang = (float)s * inv_freq;
    float sn, cs;
    sincosf(ang, &sn, &cs);

    float2 x = *(float2*)(X + row * HDIM + 2 * j);
    float2 y;
    y.x = x.x * cs - x.y * sn;
    y.y = x.y * cs + x.x * sn;
    *(float2*)(X + row * HDIM + 2 * j) = y;
}

// ===========================================================================
// Tensor-core flash attention.
// CTA = one (b,h) x 128 q rows. 4 warps x 32 q rows. 64-key tiles.
// S = Q·K^T via bf16 split-3; softmax in base-2 (FFMA exp2); O = P·V split-3.
// ===========================================================================
constexpr int QB  = 128;   // q rows per CTA
constexpr int KTL = 64;    // keys per tile
constexpr int PQ  = 72;    // smem pitch (bf16 elems)

constexpr int OFF_QH = 0;
constexpr int OFF_QL = OFF_QH + QB * PQ * 2;
constexpr int OFF_KH = OFF_QL + QB * PQ * 2;
constexpr int OFF_KL = OFF_KH + KTL * PQ * 2;
constexpr int OFF_VH = OFF_KL + KTL * PQ * 2;
constexpr int OFF_VL = OFF_VH + KTL * PQ * 2;
constexpr int OFF_MB = OFF_VL + KTL * PQ * 2;
constexpr int SMEM_ATTN = OFF_MB + KTL * 4;

constexpr float SCALE2 = 0.18033688011f;      // 0.125 * log2(e)
constexpr float MBIAS2 = -14426.950409f;      // -10000 * log2(e)

__global__ void __launch_bounds__(128, 1)
attn_mma_kernel(const int* __restrict__ mask)
{
    extern __shared__ char sm[];
    __nv_bfloat16* sQh = (__nv_bfloat16*)(sm + OFF_QH);
    __nv_bfloat16* sQl = (__nv_bfloat16*)(sm + OFF_QL);
    __nv_bfloat16* sKh = (__nv_bfloat16*)(sm + OFF_KH);
    __nv_bfloat16* sKl = (__nv_bfloat16*)(sm + OFF_KL);
    __nv_bfloat16* sVh = (__nv_bfloat16*)(sm + OFF_VH);
    __nv_bfloat16* sVl = (__nv_bfloat16*)(sm + OFF_VL);
    float* sMb = (float*)(sm + OFF_MB);

    const int tid = threadIdx.x;
    const int wid = tid >> 5, lane = tid & 31;
    const int bh = blockIdx.y, b = bh >> 4, h = bh & 15;
    const int q0 = blockIdx.x * QB;

    const float* Qg = g_q + ((size_t)bh * SEQ + q0) * HDIM;
    const float* Kg = g_k + (size_t)bh * SEQ * HDIM;
    const float* Vg = g_v + (size_t)bh * SEQ * HDIM;

    // ---- load Q block (row = tid), convert hi/lo ----
    {
        const float4* src = (const float4*)(Qg + (size_t)tid * HDIM);
        __nv_bfloat16* dh = sQh + tid * PQ;
        __nv_bfloat16* dl = sQl + tid * PQ;
        #pragma unroll
        for (int i = 0; i < 16; i++) {
            uint2 hi, lo;
            cvt_hl(src[i], hi, lo);
            *(uint2*)(dh + i * 4) = hi;
            *(uint2*)(dl + i * 4) = lo;
        }
    }

    float accO[2][8][4];
    #pragma unroll
    for (int mi = 0; mi < 2; mi++)
        #pragma unroll
        for (int ni = 0; ni < 8; ni++)
            #pragma unroll
            for (int v = 0; v < 4; v++) accO[mi][ni][v] = 0.0f;
    float mrow[2][2] = {{-1e30f, -1e30f}, {-1e30f, -1e30f}};
    float lrow[2][2] = {{0.0f, 0.0f}, {0.0f, 0.0f}};

    const int wq0 = wid * 32;
    const uint32_t aQh = smem_u32(sQh), aQl = smem_u32(sQl);
    const uint32_t aKh = smem_u32(sKh), aKl = smem_u32(sKl);
    const uint32_t aVh = smem_u32(sVh), aVl = smem_u32(sVl);

    // lane-address components (bf16 element offsets)
    const int qa = (lane & 15) * PQ + (lane >> 4) * 8;
    const int ka = ((lane & 7) + ((lane >> 4) & 1) * 8) * PQ + ((lane >> 3) & 1) * 8;
    const int va = ((lane & 7) + ((lane >> 3) & 1) * 8) * PQ + ((lane >> 4) & 1) * 8;

    // K/V tile global-load mapping
    const int ldk  = tid >> 1;
    const int ldc0 = (tid & 1) * 32;

    for (int kt = 0; kt < SEQ; kt += KTL) {
        __syncthreads();
        {
            const float4* ksrc = (const float4*)(Kg + (size_t)(kt + ldk) * HDIM + ldc0);
            const float4* vsrc = (const float4*)(Vg + (size_t)(kt + ldk) * HDIM + ldc0);
            __nv_bfloat16* kh = sKh + ldk * PQ + ldc0;
            __nv_bfloat16* kl = sKl + ldk * PQ + ldc0;
            __nv_bfloat16* vh = sVh + ldk * PQ + ldc0;
            __nv_bfloat16* vl = sVl + ldk * PQ + ldc0;
            #pragma unroll
            for (int i = 0; i < 8; i++) {
                uint2 hi, lo;
                cvt_hl(ksrc[i], hi, lo);
                *(uint2*)(kh + i * 4) = hi;
                *(uint2*)(kl + i * 4) = lo;
                cvt_hl(vsrc[i], hi, lo);
                *(uint2*)(vh + i * 4) = hi;
                *(uint2*)(vl + i * 4) = lo;
            }
            if (tid < KTL)
                sMb[tid] = mask[b * SEQ + kt + tid] ? 0.0f : MBIAS2;
        }
        __syncthreads();

        // per-thread mask biases for the 16 owned columns
        float bias0[8], bias1[8];
        #pragma unroll
        for (int ni = 0; ni < 8; ni++) {
            bias0[ni] = sMb[ni * 8 + (lane & 3) * 2];
            bias1[ni] = sMb[ni * 8 + (lane & 3) * 2 + 1];
        }

        // ---- S = Q K^T (split-3) ----
        float acc[2][8][4];
        #pragma unroll
        for (int mi = 0; mi < 2; mi++)
            #pragma unroll
            for (int ni = 0; ni < 8; ni++)
                #pragma unroll
                for (int v = 0; v < 4; v++) acc[mi][ni][v] = 0.0f;

        #pragma unroll
        for (int ks = 0; ks < 4; ks++) {
            uint32_t qh[2][4], ql[2][4];
            #pragma unroll
            for (int mi = 0; mi < 2; mi++) {
                const uint32_t off = 2 * ((wq0 + mi * 16) * PQ + ks * 16 + qa);
                ldm_x4(qh[mi], aQh + off);
                ldm_x4(ql[mi], aQl + off);
            }
            #pragma unroll
            for (int nip = 0; nip < 4; nip++) {
                uint32_t kh[4], kl[4];
                const uint32_t off = 2 * (nip * 16 * PQ + ks * 16 + ka);
                ldm_x4(kh, aKh + off);
                ldm_x4(kl, aKl + off);
                #pragma unroll
                for (int mi = 0; mi < 2; mi++)
                    #pragma unroll
                    for (int j = 0; j < 2; j++) {
                        const int ni = nip * 2 + j;
                        mma16816(acc[mi][ni], qh[mi], &kh[2 * j]);
                        mma16816(acc[mi][ni], qh[mi], &kl[2 * j]);
                        mma16816(acc[mi][ni], ql[mi], &kh[2 * j]);
                    }
            }
        }

        // ---- online softmax (base-2, FFMA exp) ----
        #pragma unroll
        for (int mi = 0; mi < 2; mi++) {
            #pragma unroll
            for (int half = 0; half < 2; half++) {
                float mt = -1e30f;
                #pragma unroll
                for (int ni = 0; ni < 8; ni++) {
                    float v0 = fmaf(acc[mi][ni][half * 2],     SCALE2, bias0[ni]);
                    float v1 = fmaf(acc[mi][ni][half * 2 + 1], SCALE2, bias1[ni]);
                    acc[mi][ni][half * 2]     = v0;
                    acc[mi][ni][half * 2 + 1] = v1;
                    mt = fmaxf(mt, fmaxf(v0, v1));
                }
                mt = fmaxf(mt, __shfl_xor_sync(0xFFFFFFFFu, mt, 1));
                mt = fmaxf(mt, __shfl_xor_sync(0xFFFFFFFFu, mt, 2));
                const float mold = mrow[mi][half];
                const float mnew = fmaxf(mold, mt);
                const float corr = exp2fast(mold - mnew);
                mrow[mi][half] = mnew;
                lrow[mi][half] *= corr;
                float lsum = 0.0f;
                #pragma unroll
                for (int ni = 0; ni < 8; ni++) {
                    float p0 = exp2fast(acc[mi][ni][half * 2]     - mnew);
                    float p1 = exp2fast(acc[mi][ni][half * 2 + 1] - mnew);
                    acc[mi][ni][half * 2]     = p0;
                    acc[mi][ni][half * 2 + 1] = p1;
                    lsum += p0 + p1;
                    accO[mi][ni][half * 2]     *= corr;
                    accO[mi][ni][half * 2 + 1] *= corr;
                }
                lrow[mi][half] += lsum;
            }
        }

        // ---- O += P V (split-3), P fragments built from acc registers ----
        #pragma unroll
        for (int kf = 0; kf < 4; kf++) {
            uint32_t pah[2][4], pal[2][4];
            #pragma unroll
            for (int mi = 0; mi < 2; mi++) {
                pack_hl(acc[mi][2 * kf][0],     acc[mi][2 * kf][1],     pah[mi][0], pal[mi][0]);
                pack_hl(acc[mi][2 * kf][2],     acc[mi][2 * kf][3],     pah[mi][1], pal[mi][1]);
                pack_hl(acc[mi][2 * kf + 1][0], acc[mi][2 * kf + 1][1], pah[mi][2], pal[mi][2]);
                pack_hl(acc[mi][2 * kf + 1][2], acc[mi][2 * kf + 1][3], pah[mi][3], pal[mi][3]);
            }
            #pragma unroll
            for (int nip = 0; nip < 4; nip++) {
                uint32_t vh[4], vl[4];
                const uint32_t off = 2 * (kf * 16 * PQ + nip * 16 + va);
                ldm_x4_t(vh, aVh + off);
                ldm_x4_t(vl, aVl + off);
                #pragma unroll
                for (int mi = 0; mi < 2; mi++)
                    #pragma unroll
                    for (int j = 0; j < 2; j++) {
                        const int ni = nip * 2 + j;
                        mma16816(accO[mi][ni], pah[mi], &vh[2 * j]);
                        mma16816(accO[mi][ni], pah[mi], &vl[2 * j]);
                        mma16816(accO[mi][ni], pal[mi], &vh[2 * j]);
                    }
            }
        }
    }

    // ---- epilogue: reduce l across quad, normalize, store to g_x ----
    float inv[2][2];
    #pragma unroll
    for (int mi = 0; mi < 2; mi++)
        #pragma unroll
        for (int half = 0; half < 2; half++) {
            float l = lrow[mi][half];
            l += __shfl_xor_sync(0xFFFFFFFFu, l, 1);
            l += __shfl_xor_sync(0xFFFFFFFFu, l, 2);
            inv[mi][half] = 1.0f / l;
        }

    #pragma unroll
    for (int mi = 0; mi < 2; mi++)
        #pragma unroll
        for (int ni = 0; ni < 8; ni++)
            #pragma unroll
            for (int half = 0; half < 2; half++) {
                const int row = q0 + wq0 + mi * 16 + (lane >> 2) + half * 8;
                const int col = ni * 8 + (lane & 3) * 2;
                float2 v = make_float2(accO[mi][ni][half * 2] * inv[mi][half],
                                       accO[mi][ni][half * 2 + 1] * inv[mi][half]);
                *(float2*)(g_x + ((size_t)(b * SEQ + row)) * DIM + h * HDIM + col) = v;
            }
}

// ---------------------------------------------------------------------------
// Launch
// ---------------------------------------------------------------------------
extern "C" void kernel_launch(void* const* d_in, const int* in_sizes, int n_in,
                              void* d_out, int out_size)
{
    const float* q    = (const float*)d_in[0];
    const float* k    = (const float*)d_in[1];
    const float* v    = (const float*)d_in[2];
    const int*   mask = (const int*)  d_in[3];
    const float* w_q  = (const float*)d_in[4];
    const float* w_k  = (const float*)d_in[5];
    const float* w_v  = (const float*)d_in[6];
    const float* w_o  = (const float*)d_in[7];
    float* out = (float*)d_out;

    cudaFuncSetAttribute(attn_mma_kernel,
                         cudaFuncAttributeMaxDynamicSharedMemorySize, SMEM_ATTN);

    // 1) Q/K/V projections (tensor cores, writes [b,h,s,dk] scratch)
    dim3 g1(DIM / 128, NTOK / 128, 3);
    gemm_qkv_tc<<<g1, 256>>>(q, k, v, w_q, w_k, w_v);

    // 2) RoPE on Q and K in-place
    dim3 g2((BHS * SEQ * 32) / 256, 2);
    rope_kernel<<<g2, 256>>>();

    // 3) Tensor-core flash attention
    dim3 g3(SEQ / QB, BHS);
    attn_mma_kernel<<<g3, 128, SMEM_ATTN>>>(mask);

    // 4) Output projection (tensor cores)
    dim3 g4(DIM / 128, NTOK / 128);
    gemm_out_tc<<<g4, 256>>>(w_o, out);
}